// round 1
// baseline (speedup 1.0000x reference)
#include <cuda_runtime.h>
#include <math.h>

#define N_NODES 50000
#define N_EDGES 640000
#define RAW 128
#define HID 256
#define KPAD 264            // 2*RAW+1 = 257 padded to multiple of 8
#define PIN_K (RAW + HID)   // 384

// ---------------- scratch (device globals; no allocations allowed) ----------
__device__ float g_edge_in[(size_t)N_EDGES * KPAD];   // [E,264] gathered edge input
__device__ float g_bufA[(size_t)N_EDGES * HID];       // h1 / t1 / node-hidden reuse
__device__ float g_msg[(size_t)N_EDGES * HID];        // msg
__device__ float g_t2[(size_t)N_EDGES * HID];         // t2 (pre-w3)
__device__ float g_cdiff[(size_t)N_EDGES * 3];
__device__ float g_msum[(size_t)N_NODES * HID];
__device__ float g_tsum[(size_t)N_NODES * 3];
__device__ float g_cnt[N_NODES];
__device__ float g_w1pad[KPAD * HID];                 // msg_w1 zero-padded to 264 rows
__device__ float g_pin[(size_t)N_NODES * PIN_K];      // [str | msg_sum]

__device__ __forceinline__ float silu_f(float x) {
    return x / (1.0f + __expf(-x));
}

// ---------------- generic fused SGEMM: C = act(A@B + bias) (+ resid) --------
// A[M,K] lda, B[K,N] ldb row-major, C[M,N] ldc. N multiple of 128, K multiple of 8.
template <bool ACT, bool RES>
__global__ void sgemm128(const float* __restrict__ A, int lda,
                         const float* __restrict__ B, int ldb,
                         float* __restrict__ C, int ldc,
                         const float* __restrict__ bias,
                         const float* __restrict__ resid, int ldr,
                         int M, int K)
{
    const int BM = 128, BN = 128, BK = 8;
    __shared__ float As[BK][BM];
    __shared__ float Bs[BK][BN];

    const int tid = threadIdx.x;                 // 256 threads
    const int bm = blockIdx.y * BM;
    const int bn = blockIdx.x * BN;

    const int innerRowA = tid >> 1;              // 0..127
    const int innerColA = (tid & 1) * 4;         // 0 or 4
    const int innerRowB = tid >> 5;              // 0..7
    const int innerColB = (tid & 31) * 4;        // 0..124

    const int tr = tid >> 4;                     // 0..15
    const int tc = tid & 15;                     // 0..15

    float acc[8][8];
    #pragma unroll
    for (int i = 0; i < 8; i++)
        #pragma unroll
        for (int j = 0; j < 8; j++) acc[i][j] = 0.0f;

    float regM[8], regN[8];

    for (int k0 = 0; k0 < K; k0 += BK) {
        // load A tile (transposed into As)
        const int arow = bm + innerRowA;
        float4 av = make_float4(0.f, 0.f, 0.f, 0.f);
        if (arow < M)
            av = *(const float4*)(A + (size_t)arow * lda + k0 + innerColA);
        As[innerColA + 0][innerRowA] = av.x;
        As[innerColA + 1][innerRowA] = av.y;
        As[innerColA + 2][innerRowA] = av.z;
        As[innerColA + 3][innerRowA] = av.w;

        // load B tile
        float4 bv = *(const float4*)(B + (size_t)(k0 + innerRowB) * ldb + bn + innerColB);
        *(float4*)&Bs[innerRowB][innerColB] = bv;

        __syncthreads();

        #pragma unroll
        for (int k = 0; k < BK; k++) {
            #pragma unroll
            for (int i = 0; i < 8; i++) regM[i] = As[k][tr * 8 + i];
            #pragma unroll
            for (int j = 0; j < 8; j++) regN[j] = Bs[k][tc * 8 + j];
            #pragma unroll
            for (int i = 0; i < 8; i++)
                #pragma unroll
                for (int j = 0; j < 8; j++)
                    acc[i][j] = fmaf(regM[i], regN[j], acc[i][j]);
        }
        __syncthreads();
    }

    #pragma unroll
    for (int i = 0; i < 8; i++) {
        const int row = bm + tr * 8 + i;
        if (row >= M) continue;
        #pragma unroll
        for (int j = 0; j < 8; j++) {
            const int col = bn + tc * 8 + j;
            float v = acc[i][j] + bias[col];
            if (ACT) v = silu_f(v);
            if (RES) v += resid[(size_t)row * ldr + col];
            C[(size_t)row * ldc + col] = v;
        }
    }
}

// ---------------- gather: build edge_in[E,264] and coord_diff ---------------
__global__ void gather_edges(const int* __restrict__ ei,
                             const float* __restrict__ str,
                             const float* __restrict__ coord)
{
    const int e = blockIdx.x * 8 + (threadIdx.x >> 5);
    const int lane = threadIdx.x & 31;
    if (e >= N_EDGES) return;
    const int r = ei[e];
    const int c = ei[N_EDGES + e];

    const float4* sr = (const float4*)(str + (size_t)r * RAW);
    const float4* sc = (const float4*)(str + (size_t)c * RAW);
    float4* dst = (float4*)(g_edge_in + (size_t)e * KPAD);
    dst[lane]      = sr[lane];   // cols 0..127
    dst[32 + lane] = sc[lane];   // cols 128..255

    if (lane == 0) {
        float dx = coord[r * 3 + 0] - coord[c * 3 + 0];
        float dy = coord[r * 3 + 1] - coord[c * 3 + 1];
        float dz = coord[r * 3 + 2] - coord[c * 3 + 2];
        g_cdiff[(size_t)e * 3 + 0] = dx;
        g_cdiff[(size_t)e * 3 + 1] = dy;
        g_cdiff[(size_t)e * 3 + 2] = dz;
        g_edge_in[(size_t)e * KPAD + 256] = dx * dx + dy * dy + dz * dz;
    }
    if (lane >= 25)  // zero pad cols 257..263
        g_edge_in[(size_t)e * KPAD + 232 + lane] = 0.0f;
}

// ---------------- pad msg_w1 [257,256] -> [264,256] -------------------------
__global__ void pad_w1(const float* __restrict__ w1)
{
    const int i = blockIdx.x * 256 + threadIdx.x;
    if (i >= KPAD * HID) return;
    const int k = i / HID;
    g_w1pad[i] = (k < 2 * RAW + 1) ? w1[i] : 0.0f;
}

// ---------------- per-edge gate = t2@w3; atomic segment scatter -------------
__global__ void gate_scatter(const int* __restrict__ ei,
                             const float* __restrict__ w3)
{
    const int e = blockIdx.x * 8 + (threadIdx.x >> 5);
    const int lane = threadIdx.x & 31;
    if (e >= N_EDGES) return;
    const int r = ei[e];

    const float* t2 = g_t2 + (size_t)e * HID;
    float acc = 0.0f;
    #pragma unroll
    for (int i = 0; i < 8; i++) {
        const int cidx = lane + 32 * i;
        acc += t2[cidx] * w3[cidx];
    }
    #pragma unroll
    for (int o = 16; o > 0; o >>= 1)
        acc += __shfl_xor_sync(0xffffffffu, acc, o);
    // acc == gate on all lanes

    if (lane < 3)
        atomicAdd(&g_tsum[(size_t)r * 3 + lane], g_cdiff[(size_t)e * 3 + lane] * acc);
    if (lane == 3)
        atomicAdd(&g_cnt[r], 1.0f);

    const float* msg = g_msg + (size_t)e * HID;
    #pragma unroll
    for (int i = 0; i < 8; i++) {
        const int cidx = lane + 32 * i;
        atomicAdd(&g_msum[(size_t)r * HID + cidx], msg[cidx]);
    }
}

// ---------------- build p_in = [str | msg_sum] ------------------------------
__global__ void build_pin(const float* __restrict__ str)
{
    const int idx = blockIdx.x * 256 + threadIdx.x;
    if (idx >= N_NODES * PIN_K) return;
    const int n = idx / PIN_K;
    const int c = idx - n * PIN_K;
    g_pin[idx] = (c < RAW) ? str[(size_t)n * RAW + c]
                           : g_msum[(size_t)n * HID + (c - RAW)];
}

// ---------------- coord epilogue --------------------------------------------
__global__ void coord_epilogue(const float* __restrict__ coord,
                               float* __restrict__ out_coord)
{
    const int idx = blockIdx.x * 256 + threadIdx.x;
    if (idx >= N_NODES * 3) return;
    const int n = idx / 3;
    out_coord[idx] = coord[idx] + g_tsum[idx] / fmaxf(g_cnt[n], 1.0f);
}

// ---------------- launch -----------------------------------------------------
extern "C" void kernel_launch(void* const* d_in, const int* in_sizes, int n_in,
                              void* d_out, int out_size)
{
    const int*   ei      = (const int*)  d_in[0];
    const float* str     = (const float*)d_in[1];
    const float* coord   = (const float*)d_in[2];
    const float* msg_w1  = (const float*)d_in[3];
    const float* msg_b1  = (const float*)d_in[4];
    const float* msg_w2  = (const float*)d_in[5];
    const float* msg_b2  = (const float*)d_in[6];
    const float* tr_w1   = (const float*)d_in[7];
    const float* tr_b1   = (const float*)d_in[8];
    const float* tr_w2   = (const float*)d_in[9];
    const float* tr_b2   = (const float*)d_in[10];
    const float* tr_w3   = (const float*)d_in[11];
    const float* posi_w1 = (const float*)d_in[12];
    const float* posi_b1 = (const float*)d_in[13];
    const float* posi_w2 = (const float*)d_in[14];
    const float* posi_b2 = (const float*)d_in[15];

    float* out_str   = (float*)d_out;                      // [N,128]
    float* out_coord = (float*)d_out + (size_t)N_NODES * RAW;  // [N,3]

    // symbol addresses for GEMM operands / memsets
    void *p_edge_in, *p_bufA, *p_msg, *p_t2, *p_msum, *p_tsum, *p_cnt, *p_w1pad, *p_pin;
    cudaGetSymbolAddress(&p_edge_in, g_edge_in);
    cudaGetSymbolAddress(&p_bufA,    g_bufA);
    cudaGetSymbolAddress(&p_msg,     g_msg);
    cudaGetSymbolAddress(&p_t2,      g_t2);
    cudaGetSymbolAddress(&p_msum,    g_msum);
    cudaGetSymbolAddress(&p_tsum,    g_tsum);
    cudaGetSymbolAddress(&p_cnt,     g_cnt);
    cudaGetSymbolAddress(&p_w1pad,   g_w1pad);
    cudaGetSymbolAddress(&p_pin,     g_pin);

    cudaMemsetAsync(p_msum, 0, (size_t)N_NODES * HID * sizeof(float));
    cudaMemsetAsync(p_tsum, 0, (size_t)N_NODES * 3 * sizeof(float));
    cudaMemsetAsync(p_cnt,  0, (size_t)N_NODES * sizeof(float));

    pad_w1<<<(KPAD * HID + 255) / 256, 256>>>(msg_w1);
    gather_edges<<<N_EDGES / 8, 256>>>(ei, str, coord);

    const int GM_E = (N_EDGES + 127) / 128;   // 5000
    const int GM_N = (N_NODES + 127) / 128;   // 391

    // h1 = silu(edge_in @ w1pad + b1)
    sgemm128<true, false><<<dim3(HID / 128, GM_E), 256>>>(
        (const float*)p_edge_in, KPAD, (const float*)p_w1pad, HID,
        (float*)p_bufA, HID, msg_b1, nullptr, 0, N_EDGES, KPAD);
    // msg = silu(h1 @ msg_w2 + b2)
    sgemm128<true, false><<<dim3(HID / 128, GM_E), 256>>>(
        (const float*)p_bufA, HID, msg_w2, HID,
        (float*)p_msg, HID, msg_b2, nullptr, 0, N_EDGES, HID);
    // t1 = silu(msg @ tr_w1 + tr_b1)
    sgemm128<true, false><<<dim3(HID / 128, GM_E), 256>>>(
        (const float*)p_msg, HID, tr_w1, HID,
        (float*)p_bufA, HID, tr_b1, nullptr, 0, N_EDGES, HID);
    // t2 = silu(t1 @ tr_w2 + tr_b2)
    sgemm128<true, false><<<dim3(HID / 128, GM_E), 256>>>(
        (const float*)p_bufA, HID, tr_w2, HID,
        (float*)p_t2, HID, tr_b2, nullptr, 0, N_EDGES, HID);

    // gate + segment scatter (trans_sum, cnt, msg_sum)
    gate_scatter<<<N_EDGES / 8, 256>>>(ei, tr_w3);

    // node MLP
    build_pin<<<(N_NODES * PIN_K + 255) / 256, 256>>>(str);
    sgemm128<true, false><<<dim3(HID / 128, GM_N), 256>>>(
        (const float*)p_pin, PIN_K, posi_w1, HID,
        (float*)p_bufA, HID, posi_b1, nullptr, 0, N_NODES, PIN_K);
    sgemm128<false, true><<<dim3(RAW / 128, GM_N), 256>>>(
        (const float*)p_bufA, HID, posi_w2, RAW,
        out_str, RAW, posi_b2, str, RAW, N_NODES, HID);

    coord_epilogue<<<(N_NODES * 3 + 255) / 256, 256>>>(coord, out_coord);
}

// round 2
// speedup vs baseline: 2.7047x; 2.7047x over previous
#include <cuda_runtime.h>
#include <math.h>

#define N_NODES 50000
#define N_EDGES 640000
#define RAW 128
#define HID 256
#define KPAD 288            // 2*RAW+1 = 257 padded to multiple of 32
#define PIN_K (RAW + HID)   // 384

// ---------------- scratch (device globals; no allocations allowed) ----------
__device__ float g_edge_in[(size_t)N_EDGES * KPAD];   // [E,288] gathered edge input
__device__ float g_bufA[(size_t)N_EDGES * HID];       // h1 / t1 / node-hidden reuse
__device__ float g_msg[(size_t)N_EDGES * HID];        // msg
__device__ float g_t2[(size_t)N_EDGES * HID];         // t2 (pre-w3)
__device__ float g_cdiff[(size_t)N_EDGES * 3];
__device__ float g_msum[(size_t)N_NODES * HID];
__device__ float g_tsum[(size_t)N_NODES * 3];
__device__ float g_cnt[N_NODES];
__device__ float g_w1pad[KPAD * HID];                 // msg_w1 zero-padded to 288 rows
__device__ float g_pin[(size_t)N_NODES * PIN_K];      // [str | msg_sum]

__device__ __forceinline__ float silu_f(float x) {
    return x / (1.0f + __expf(-x));
}

__device__ __forceinline__ unsigned f2tf(float x) {
    unsigned r;
    asm("cvt.rna.tf32.f32 %0, %1;" : "=r"(r) : "f"(x));
    return r;
}

// ---------------- TF32 tensor-core GEMM: C = act(A@B + bias) (+ resid) ------
// A[M,K] lda fp32, B[K,N] ldb fp32 row-major, C[M,N] ldc fp32.
// N multiple of 128, K multiple of 32. M arbitrary (predicated).
// Block: 256 threads (8 warps, 2x4 warp grid), tile 128x128, BK=32.
#define AS_STRIDE 36
#define BS_STRIDE 136

template <bool ACT, bool RES>
__global__ void __launch_bounds__(256, 2)
tgemm128(const float* __restrict__ A, int lda,
         const float* __restrict__ B, int ldb,
         float* __restrict__ C, int ldc,
         const float* __restrict__ bias,
         const float* __restrict__ resid, int ldr,
         int M, int K)
{
    __shared__ unsigned As[128 * AS_STRIDE];   // [row][k]
    __shared__ unsigned Bs[32 * BS_STRIDE];    // [k][col]

    const int tid = threadIdx.x;
    const int wid = tid >> 5;
    const int lane = tid & 31;
    const int gid = lane >> 2;     // 0..7
    const int ctid = lane & 3;     // 0..3

    const int warpm = wid >> 2;    // 0..1  -> 64 rows
    const int warpn = wid & 3;     // 0..3  -> 32 cols

    const int bm = blockIdx.y * 128;
    const int bn = blockIdx.x * 128;

    float acc[4][4][4];
    #pragma unroll
    for (int i = 0; i < 4; i++)
        #pragma unroll
        for (int j = 0; j < 4; j++)
            #pragma unroll
            for (int q = 0; q < 4; q++) acc[i][j][q] = 0.0f;

    for (int k0 = 0; k0 < K; k0 += 32) {
        // ---- stage A tile: 128 x 32 floats, 4 float4 per thread ----
        #pragma unroll
        for (int i = 0; i < 4; i++) {
            const int idx = tid + i * 256;        // 0..1023
            const int row = idx >> 3;             // 0..127
            const int c4  = (idx & 7) * 4;        // 0..28
            float4 v = make_float4(0.f, 0.f, 0.f, 0.f);
            if (bm + row < M)
                v = *(const float4*)(A + (size_t)(bm + row) * lda + k0 + c4);
            unsigned* dst = &As[row * AS_STRIDE + c4];
            dst[0] = f2tf(v.x); dst[1] = f2tf(v.y);
            dst[2] = f2tf(v.z); dst[3] = f2tf(v.w);
        }
        // ---- stage B tile: 32 x 128 floats ----
        #pragma unroll
        for (int i = 0; i < 4; i++) {
            const int idx = tid + i * 256;
            const int row = idx >> 5;              // 0..31
            const int c4  = (idx & 31) * 4;        // 0..124
            float4 v = *(const float4*)(B + (size_t)(k0 + row) * ldb + bn + c4);
            unsigned* dst = &Bs[row * BS_STRIDE + c4];
            dst[0] = f2tf(v.x); dst[1] = f2tf(v.y);
            dst[2] = f2tf(v.z); dst[3] = f2tf(v.w);
        }
        __syncthreads();

        #pragma unroll
        for (int kk = 0; kk < 32; kk += 8) {
            unsigned a[4][4], b[4][2];
            #pragma unroll
            for (int mf = 0; mf < 4; mf++) {
                const int rb = warpm * 64 + mf * 16;
                a[mf][0] = As[(rb + gid)     * AS_STRIDE + kk + ctid];
                a[mf][1] = As[(rb + gid + 8) * AS_STRIDE + kk + ctid];
                a[mf][2] = As[(rb + gid)     * AS_STRIDE + kk + ctid + 4];
                a[mf][3] = As[(rb + gid + 8) * AS_STRIDE + kk + ctid + 4];
            }
            #pragma unroll
            for (int nf = 0; nf < 4; nf++) {
                const int cb = warpn * 32 + nf * 8;
                b[nf][0] = Bs[(kk + ctid)     * BS_STRIDE + cb + gid];
                b[nf][1] = Bs[(kk + ctid + 4) * BS_STRIDE + cb + gid];
            }
            #pragma unroll
            for (int mf = 0; mf < 4; mf++)
                #pragma unroll
                for (int nf = 0; nf < 4; nf++) {
                    asm volatile(
                        "mma.sync.aligned.m16n8k8.row.col.f32.tf32.tf32.f32 "
                        "{%0,%1,%2,%3}, {%4,%5,%6,%7}, {%8,%9}, {%0,%1,%2,%3};"
                        : "+f"(acc[mf][nf][0]), "+f"(acc[mf][nf][1]),
                          "+f"(acc[mf][nf][2]), "+f"(acc[mf][nf][3])
                        : "r"(a[mf][0]), "r"(a[mf][1]), "r"(a[mf][2]), "r"(a[mf][3]),
                          "r"(b[nf][0]), "r"(b[nf][1]));
                }
        }
        __syncthreads();
    }

    // ---- epilogue ----
    #pragma unroll
    for (int mf = 0; mf < 4; mf++) {
        #pragma unroll
        for (int nf = 0; nf < 4; nf++) {
            const int col0 = bn + warpn * 32 + nf * 8 + ctid * 2;
            const float b0 = bias[col0], b1 = bias[col0 + 1];
            #pragma unroll
            for (int h = 0; h < 2; h++) {   // h=0: rows gid, h=1: rows gid+8
                const int row = bm + warpm * 64 + mf * 16 + gid + h * 8;
                if (row >= M) continue;
                float v0 = acc[mf][nf][h * 2 + 0] + b0;
                float v1 = acc[mf][nf][h * 2 + 1] + b1;
                if (ACT) { v0 = silu_f(v0); v1 = silu_f(v1); }
                if (RES) {
                    v0 += resid[(size_t)row * ldr + col0];
                    v1 += resid[(size_t)row * ldr + col0 + 1];
                }
                float2 out = make_float2(v0, v1);
                *(float2*)(C + (size_t)row * ldc + col0) = out;
            }
        }
    }
}

// ---------------- gather: build edge_in[E,288] and coord_diff ---------------
__global__ void gather_edges(const int* __restrict__ ei,
                             const float* __restrict__ str,
                             const float* __restrict__ coord)
{
    const int e = blockIdx.x * 8 + (threadIdx.x >> 5);
    const int lane = threadIdx.x & 31;
    if (e >= N_EDGES) return;
    const int r = ei[e];
    const int c = ei[N_EDGES + e];

    const float4* sr = (const float4*)(str + (size_t)r * RAW);
    const float4* sc = (const float4*)(str + (size_t)c * RAW);
    float4* dst = (float4*)(g_edge_in + (size_t)e * KPAD);
    dst[lane]      = sr[lane];   // cols 0..127
    dst[32 + lane] = sc[lane];   // cols 128..255

    if (lane == 0) {
        float dx = coord[r * 3 + 0] - coord[c * 3 + 0];
        float dy = coord[r * 3 + 1] - coord[c * 3 + 1];
        float dz = coord[r * 3 + 2] - coord[c * 3 + 2];
        g_cdiff[(size_t)e * 3 + 0] = dx;
        g_cdiff[(size_t)e * 3 + 1] = dy;
        g_cdiff[(size_t)e * 3 + 2] = dz;
        g_edge_in[(size_t)e * KPAD + 256] = dx * dx + dy * dy + dz * dz;
    } else {
        g_edge_in[(size_t)e * KPAD + 256 + lane] = 0.0f;  // cols 257..287
    }
}

// ---------------- pad msg_w1 [257,256] -> [288,256] -------------------------
__global__ void pad_w1(const float* __restrict__ w1)
{
    const int i = blockIdx.x * 256 + threadIdx.x;
    if (i >= KPAD * HID) return;
    const int k = i / HID;
    g_w1pad[i] = (k < 2 * RAW + 1) ? w1[i] : 0.0f;
}

// ---------------- per-edge gate = t2@w3; atomic segment scatter -------------
__global__ void gate_scatter(const int* __restrict__ ei,
                             const float* __restrict__ w3)
{
    const int e = blockIdx.x * 8 + (threadIdx.x >> 5);
    const int lane = threadIdx.x & 31;
    if (e >= N_EDGES) return;
    const int r = ei[e];

    const float* t2 = g_t2 + (size_t)e * HID;
    float acc = 0.0f;
    #pragma unroll
    for (int i = 0; i < 8; i++) {
        const int cidx = lane + 32 * i;
        acc += t2[cidx] * w3[cidx];
    }
    #pragma unroll
    for (int o = 16; o > 0; o >>= 1)
        acc += __shfl_xor_sync(0xffffffffu, acc, o);
    // acc == gate on all lanes

    if (lane < 3)
        atomicAdd(&g_tsum[(size_t)r * 3 + lane], g_cdiff[(size_t)e * 3 + lane] * acc);
    if (lane == 3)
        atomicAdd(&g_cnt[r], 1.0f);

    const float* msg = g_msg + (size_t)e * HID;
    #pragma unroll
    for (int i = 0; i < 8; i++) {
        const int cidx = lane + 32 * i;
        atomicAdd(&g_msum[(size_t)r * HID + cidx], msg[cidx]);
    }
}

// ---------------- build p_in = [str | msg_sum] ------------------------------
__global__ void build_pin(const float* __restrict__ str)
{
    const int idx = blockIdx.x * 256 + threadIdx.x;
    if (idx >= N_NODES * PIN_K) return;
    const int n = idx / PIN_K;
    const int c = idx - n * PIN_K;
    g_pin[idx] = (c < RAW) ? str[(size_t)n * RAW + c]
                           : g_msum[(size_t)n * HID + (c - RAW)];
}

// ---------------- coord epilogue --------------------------------------------
__global__ void coord_epilogue(const float* __restrict__ coord,
                               float* __restrict__ out_coord)
{
    const int idx = blockIdx.x * 256 + threadIdx.x;
    if (idx >= N_NODES * 3) return;
    const int n = idx / 3;
    out_coord[idx] = coord[idx] + g_tsum[idx] / fmaxf(g_cnt[n], 1.0f);
}

// ---------------- launch -----------------------------------------------------
extern "C" void kernel_launch(void* const* d_in, const int* in_sizes, int n_in,
                              void* d_out, int out_size)
{
    const int*   ei      = (const int*)  d_in[0];
    const float* str     = (const float*)d_in[1];
    const float* coord   = (const float*)d_in[2];
    const float* msg_w1  = (const float*)d_in[3];
    const float* msg_b1  = (const float*)d_in[4];
    const float* msg_w2  = (const float*)d_in[5];
    const float* msg_b2  = (const float*)d_in[6];
    const float* tr_w1   = (const float*)d_in[7];
    const float* tr_b1   = (const float*)d_in[8];
    const float* tr_w2   = (const float*)d_in[9];
    const float* tr_b2   = (const float*)d_in[10];
    const float* tr_w3   = (const float*)d_in[11];
    const float* posi_w1 = (const float*)d_in[12];
    const float* posi_b1 = (const float*)d_in[13];
    const float* posi_w2 = (const float*)d_in[14];
    const float* posi_b2 = (const float*)d_in[15];

    float* out_str   = (float*)d_out;                          // [N,128]
    float* out_coord = (float*)d_out + (size_t)N_NODES * RAW;  // [N,3]

    void *p_edge_in, *p_bufA, *p_msg, *p_t2, *p_msum, *p_tsum, *p_cnt, *p_w1pad, *p_pin;
    cudaGetSymbolAddress(&p_edge_in, g_edge_in);
    cudaGetSymbolAddress(&p_bufA,    g_bufA);
    cudaGetSymbolAddress(&p_msg,     g_msg);
    cudaGetSymbolAddress(&p_t2,      g_t2);
    cudaGetSymbolAddress(&p_msum,    g_msum);
    cudaGetSymbolAddress(&p_tsum,    g_tsum);
    cudaGetSymbolAddress(&p_cnt,     g_cnt);
    cudaGetSymbolAddress(&p_w1pad,   g_w1pad);
    cudaGetSymbolAddress(&p_pin,     g_pin);

    cudaMemsetAsync(p_msum, 0, (size_t)N_NODES * HID * sizeof(float));
    cudaMemsetAsync(p_tsum, 0, (size_t)N_NODES * 3 * sizeof(float));
    cudaMemsetAsync(p_cnt,  0, (size_t)N_NODES * sizeof(float));

    pad_w1<<<(KPAD * HID + 255) / 256, 256>>>(msg_w1);
    gather_edges<<<N_EDGES / 8, 256>>>(ei, str, coord);

    const int GM_E = N_EDGES / 128;            // 5000
    const int GM_N = (N_NODES + 127) / 128;    // 391

    // h1 = silu(edge_in @ w1pad + b1)
    tgemm128<true, false><<<dim3(HID / 128, GM_E), 256>>>(
        (const float*)p_edge_in, KPAD, (const float*)p_w1pad, HID,
        (float*)p_bufA, HID, msg_b1, nullptr, 0, N_EDGES, KPAD);
    // msg = silu(h1 @ msg_w2 + b2)
    tgemm128<true, false><<<dim3(HID / 128, GM_E), 256>>>(
        (const float*)p_bufA, HID, msg_w2, HID,
        (float*)p_msg, HID, msg_b2, nullptr, 0, N_EDGES, HID);
    // t1 = silu(msg @ tr_w1 + tr_b1)
    tgemm128<true, false><<<dim3(HID / 128, GM_E), 256>>>(
        (const float*)p_msg, HID, tr_w1, HID,
        (float*)p_bufA, HID, tr_b1, nullptr, 0, N_EDGES, HID);
    // t2 = silu(t1 @ tr_w2 + tr_b2)
    tgemm128<true, false><<<dim3(HID / 128, GM_E), 256>>>(
        (const float*)p_bufA, HID, tr_w2, HID,
        (float*)p_t2, HID, tr_b2, nullptr, 0, N_EDGES, HID);

    // gate + segment scatter (trans_sum, cnt, msg_sum)
    gate_scatter<<<N_EDGES / 8, 256>>>(ei, tr_w3);

    // node MLP
    build_pin<<<(N_NODES * PIN_K + 255) / 256, 256>>>(str);
    tgemm128<true, false><<<dim3(HID / 128, GM_N), 256>>>(
        (const float*)p_pin, PIN_K, posi_w1, HID,
        (float*)p_bufA, HID, posi_b1, nullptr, 0, N_NODES, PIN_K);
    tgemm128<false, true><<<dim3(RAW / 128, GM_N), 256>>>(
        (const float*)p_bufA, HID, posi_w2, RAW,
        out_str, RAW, posi_b2, str, RAW, N_NODES, HID);

    coord_epilogue<<<(N_NODES * 3 + 255) / 256, 256>>>(coord, out_coord);
}

// round 4
// speedup vs baseline: 2.7880x; 1.0308x over previous
#include <cuda_runtime.h>
#include <cstdint>
#include <math.h>

#define N_NODES 50000
#define N_EDGES 640000
#define RAW 128
#define HID 256
#define KPAD 288            // 2*RAW+1 = 257 padded to multiple of 32
#define PIN_K (RAW + HID)   // 384

// ---------------- scratch (device globals; no allocations allowed) ----------
__device__ float g_edge_in[(size_t)N_EDGES * KPAD];
__device__ float g_bufA[(size_t)N_EDGES * HID];
__device__ float g_msg[(size_t)N_EDGES * HID];
__device__ float g_t2[(size_t)N_EDGES * HID];
__device__ float g_cdiff[(size_t)N_EDGES * 3];
__device__ float g_msum[(size_t)N_NODES * HID];
__device__ float g_tsum[(size_t)N_NODES * 3];
__device__ float g_cnt[N_NODES];
__device__ float g_pin[(size_t)N_NODES * PIN_K];
// transposed + tf32-rounded weights, [N,K] K-major, packed:
__device__ float g_wt[401408];
#define WT1_OFF 0         // [256,288]
#define WT2_OFF 73728     // [256,256]
#define WT3_OFF 139264    // [256,256]
#define WT4_OFF 204800    // [256,256]
#define WT5_OFF 270336    // [256,384]
#define WT6_OFF 368640    // [128,256]

__device__ __forceinline__ float silu_f(float x) { return x / (1.0f + __expf(-x)); }
__device__ __forceinline__ unsigned f2tf(float x) {
    unsigned r; asm("cvt.rna.tf32.f32 %0, %1;" : "=r"(r) : "f"(x)); return r;
}
__device__ __forceinline__ float rnd_tf(float x) { return __uint_as_float(f2tf(x)); }

__device__ __forceinline__ uint32_t smem_u32(const void* p) {
    uint32_t a;
    asm("{ .reg .u64 t; cvta.to.shared.u64 t, %1; cvt.u32.u64 %0, t; }" : "=r"(a) : "l"(p));
    return a;
}
__device__ __forceinline__ void cp16(uint32_t dst, const void* src, uint32_t sz) {
    asm volatile("cp.async.cg.shared.global [%0], [%1], 16, %2;" :: "r"(dst), "l"(src), "r"(sz) : "memory");
}
__device__ __forceinline__ void ldsm4(uint32_t& r0, uint32_t& r1, uint32_t& r2, uint32_t& r3,
                                      uint32_t addr) {
    asm volatile("ldmatrix.sync.aligned.m8n8.x4.shared.b16 {%0,%1,%2,%3}, [%4];"
                 : "=r"(r0), "=r"(r1), "=r"(r2), "=r"(r3) : "r"(addr));
}

// ================= TF32 mma.sync GEMM, ldmatrix + cp.async pipeline =========
// C[M,Ntot] = act(A[M,K] @ Bt[Ntot,K]^T + bias) (+resid).
// A[M,K] lda, Bt[Ntot,K] ldb, both row-major fp32 (values pre-rounded to tf32).
// Tile 128x128, BK=32, 256 threads (8 warps, 2x4), 2-stage cp.async pipeline.
#define TILE_B 16384          // one 128x32 fp32 tile
#define STAGE_B (2 * TILE_B)  // A + B per stage

template <bool ACT, bool RES, bool RND>
__global__ void __launch_bounds__(256, 2)
tgemm(const float* __restrict__ A, int lda,
      const float* __restrict__ Bt, int ldb,
      float* __restrict__ C, int ldc,
      const float* __restrict__ bias,
      const float* __restrict__ resid, int ldr,
      int M, int K)
{
    extern __shared__ char smem[];
    const uint32_t sb = smem_u32(smem);

    const int tid = threadIdx.x;
    const int wid = tid >> 5;
    const int lane = tid & 31;
    const int gid = lane >> 2;     // 0..7
    const int ctid = lane & 3;     // 0..3
    const int warpm = wid >> 2;    // 0..1 -> 64 rows
    const int warpn = wid & 3;     // 0..3 -> 32 cols

    const int bm = blockIdx.y * 128;
    const int bn = blockIdx.x * 128;
    const int KT = K >> 5;

    // ---- staging assignment: thread t loads row t>>1, 4 chunks of 16B -----
    const int sRow = tid >> 1;            // 0..127
    const int sHalf = tid & 1;            // 0..1
    const uint32_t sSw = (uint32_t)(sRow & 7);
    const bool aOK = (bm + sRow) < M;
    const float* aSrcRow = A + (size_t)(aOK ? (bm + sRow) : 0) * lda + sHalf * 16;
    const float* bSrcRow = Bt + (size_t)(bn + sRow) * ldb + sHalf * 16;
    const uint32_t aDstRow = sb + (uint32_t)sRow * 128;
    const uint32_t bDstRow = aDstRow + TILE_B;

    // ---- fragment (ldmatrix) addressing ------------------------------------
    const uint32_t fRow = (uint32_t)(lane & 15);
    const uint32_t fHi  = (uint32_t)(lane >> 4);
    const uint32_t fSx  = (uint32_t)(lane & 7);
    const uint32_t aFragBase = sb + ((uint32_t)warpm * 64 + fRow) * 128;
    const uint32_t bFragBase = sb + TILE_B + ((uint32_t)warpn * 32 + fRow) * 128;

    float acc[4][4][4];
    #pragma unroll
    for (int i = 0; i < 4; i++)
        #pragma unroll
        for (int j = 0; j < 4; j++)
            #pragma unroll
            for (int q = 0; q < 4; q++) acc[i][j][q] = 0.0f;

    auto stage_load = [&](int kt, int s) {
        const uint32_t soff = (uint32_t)s * STAGE_B;
        const float* aS = aSrcRow + kt * 32;
        const float* bS = bSrcRow + kt * 32;
        #pragma unroll
        for (int i = 0; i < 4; i++) {
            const uint32_t c = (uint32_t)(sHalf * 4 + i);
            const uint32_t off = ((c ^ sSw) << 4);
            cp16(soff + aDstRow + off, aS + i * 4, aOK ? 16u : 0u);
            cp16(soff + bDstRow + off, bS + i * 4, 16u);
        }
        asm volatile("cp.async.commit_group;" ::: "memory");
    };

    stage_load(0, 0);

    for (int kt = 0; kt < KT; kt++) {
        const int cur = kt & 1;
        if (kt + 1 < KT) {
            stage_load(kt + 1, cur ^ 1);
            asm volatile("cp.async.wait_group 1;" ::: "memory");
        } else {
            asm volatile("cp.async.wait_group 0;" ::: "memory");
        }
        __syncthreads();

        const uint32_t soff = (uint32_t)cur * STAGE_B;
        #pragma unroll
        for (int kk = 0; kk < 32; kk += 8) {
            const uint32_t kc = (uint32_t)(kk >> 2);
            const uint32_t koff = (((kc + fHi) ^ fSx) << 4);
            uint32_t a[4][4], b[4][2];
            #pragma unroll
            for (int mf = 0; mf < 4; mf++)
                ldsm4(a[mf][0], a[mf][1], a[mf][2], a[mf][3],
                      soff + aFragBase + (uint32_t)mf * 2048 + koff);
            #pragma unroll
            for (int p = 0; p < 2; p++)
                ldsm4(b[2*p][0], b[2*p+1][0], b[2*p][1], b[2*p+1][1],
                      soff + bFragBase + (uint32_t)p * 2048 + koff);
            #pragma unroll
            for (int mf = 0; mf < 4; mf++)
                #pragma unroll
                for (int nf = 0; nf < 4; nf++) {
                    asm volatile(
                        "mma.sync.aligned.m16n8k8.row.col.f32.tf32.tf32.f32 "
                        "{%0,%1,%2,%3}, {%4,%5,%6,%7}, {%8,%9}, {%0,%1,%2,%3};"
                        : "+f"(acc[mf][nf][0]), "+f"(acc[mf][nf][1]),
                          "+f"(acc[mf][nf][2]), "+f"(acc[mf][nf][3])
                        : "r"(a[mf][0]), "r"(a[mf][1]), "r"(a[mf][2]), "r"(a[mf][3]),
                          "r"(b[nf][0]), "r"(b[nf][1]));
                }
        }
        __syncthreads();
    }

    // ---- epilogue -----------------------------------------------------------
    #pragma unroll
    for (int mf = 0; mf < 4; mf++) {
        #pragma unroll
        for (int nf = 0; nf < 4; nf++) {
            const int col0 = bn + warpn * 32 + nf * 8 + ctid * 2;
            const float b0 = bias[col0], b1 = bias[col0 + 1];
            #pragma unroll
            for (int h = 0; h < 2; h++) {
                const int row = bm + warpm * 64 + mf * 16 + gid + h * 8;
                if (row >= M) continue;
                float v0 = acc[mf][nf][h * 2 + 0] + b0;
                float v1 = acc[mf][nf][h * 2 + 1] + b1;
                if (ACT) { v0 = silu_f(v0); v1 = silu_f(v1); }
                if (RES) {
                    v0 += resid[(size_t)row * ldr + col0];
                    v1 += resid[(size_t)row * ldr + col0 + 1];
                }
                if (RND) { v0 = rnd_tf(v0); v1 = rnd_tf(v1); }
                *(float2*)(C + (size_t)row * ldc + col0) = make_float2(v0, v1);
            }
        }
    }
}

// ---------------- weight transpose + tf32 round -----------------------------
__global__ void transpose_round(const float* __restrict__ in, float* __restrict__ out,
                                int K, int N)
{   // in [K,N] -> out [N,K], rounded
    const int i = blockIdx.x * 256 + threadIdx.x;
    if (i >= K * N) return;
    const int n = i / K, k = i - n * K;
    out[i] = rnd_tf(in[(size_t)k * N + n]);
}
__global__ void transpose_w1(const float* __restrict__ w1, float* __restrict__ out)
{   // w1 [257,256] -> out [256,288], zero-padded, rounded
    const int i = blockIdx.x * 256 + threadIdx.x;
    if (i >= 256 * KPAD) return;
    const int n = i / KPAD, k = i - n * KPAD;
    out[i] = (k < 2 * RAW + 1) ? rnd_tf(w1[(size_t)k * HID + n]) : 0.0f;
}

// ---------------- gather: build edge_in[E,288] (tf32-rounded) ----------------
__global__ void gather_edges(const int* __restrict__ ei,
                             const float* __restrict__ str,
                             const float* __restrict__ coord)
{
    const int e = blockIdx.x * 8 + (threadIdx.x >> 5);
    const int lane = threadIdx.x & 31;
    if (e >= N_EDGES) return;
    const int r = ei[e];
    const int c = ei[N_EDGES + e];

    const float4* sr = (const float4*)(str + (size_t)r * RAW);
    const float4* sc = (const float4*)(str + (size_t)c * RAW);
    float4* dst = (float4*)(g_edge_in + (size_t)e * KPAD);
    float4 a = sr[lane], b = sc[lane];
    a.x=rnd_tf(a.x); a.y=rnd_tf(a.y); a.z=rnd_tf(a.z); a.w=rnd_tf(a.w);
    b.x=rnd_tf(b.x); b.y=rnd_tf(b.y); b.z=rnd_tf(b.z); b.w=rnd_tf(b.w);
    dst[lane]      = a;
    dst[32 + lane] = b;

    if (lane == 0) {
        float dx = coord[r*3+0] - coord[c*3+0];
        float dy = coord[r*3+1] - coord[c*3+1];
        float dz = coord[r*3+2] - coord[c*3+2];
        g_cdiff[(size_t)e*3+0] = dx;
        g_cdiff[(size_t)e*3+1] = dy;
        g_cdiff[(size_t)e*3+2] = dz;
        g_edge_in[(size_t)e*KPAD + 256] = rnd_tf(dx*dx + dy*dy + dz*dz);
    } else {
        g_edge_in[(size_t)e*KPAD + 256 + lane] = 0.0f;
    }
}

// ---------------- per-edge gate = t2@w3; atomic segment scatter --------------
__global__ void gate_scatter(const int* __restrict__ ei,
                             const float* __restrict__ w3)
{
    const int e = blockIdx.x * 8 + (threadIdx.x >> 5);
    const int lane = threadIdx.x & 31;
    if (e >= N_EDGES) return;
    const int r = ei[e];

    const float* t2 = g_t2 + (size_t)e * HID;
    float acc = 0.0f;
    #pragma unroll
    for (int i = 0; i < 8; i++) acc += t2[lane + 32*i] * w3[lane + 32*i];
    #pragma unroll
    for (int o = 16; o > 0; o >>= 1) acc += __shfl_xor_sync(0xffffffffu, acc, o);

    if (lane < 3)
        atomicAdd(&g_tsum[(size_t)r*3 + lane], g_cdiff[(size_t)e*3 + lane] * acc);
    if (lane == 3)
        atomicAdd(&g_cnt[r], 1.0f);

    const float* msg = g_msg + (size_t)e * HID;
    #pragma unroll
    for (int i = 0; i < 8; i++)
        atomicAdd(&g_msum[(size_t)r*HID + lane + 32*i], msg[lane + 32*i]);
}

// ---------------- build p_in = [str | msg_sum], rounded ----------------------
__global__ void build_pin(const float* __restrict__ str)
{
    const int idx = blockIdx.x * 256 + threadIdx.x;
    if (idx >= N_NODES * PIN_K) return;
    const int n = idx / PIN_K;
    const int c = idx - n * PIN_K;
    g_pin[idx] = rnd_tf((c < RAW) ? str[(size_t)n*RAW + c]
                                  : g_msum[(size_t)n*HID + (c - RAW)]);
}

// ---------------- coord epilogue ---------------------------------------------
__global__ void coord_epilogue(const float* __restrict__ coord,
                               float* __restrict__ out_coord)
{
    const int idx = blockIdx.x * 256 + threadIdx.x;
    if (idx >= N_NODES * 3) return;
    const int n = idx / 3;
    out_coord[idx] = coord[idx] + g_tsum[idx] / fmaxf(g_cnt[n], 1.0f);
}

// ---------------- launch ------------------------------------------------------
extern "C" void kernel_launch(void* const* d_in, const int* in_sizes, int n_in,
                              void* d_out, int out_size)
{
    const int*   ei      = (const int*)  d_in[0];
    const float* str     = (const float*)d_in[1];
    const float* coord   = (const float*)d_in[2];
    const float* msg_w1  = (const float*)d_in[3];
    const float* msg_b1  = (const float*)d_in[4];
    const float* msg_w2  = (const float*)d_in[5];
    const float* msg_b2  = (const float*)d_in[6];
    const float* tr_w1   = (const float*)d_in[7];
    const float* tr_b1   = (const float*)d_in[8];
    const float* tr_w2   = (const float*)d_in[9];
    const float* tr_b2   = (const float*)d_in[10];
    const float* tr_w3   = (const float*)d_in[11];
    const float* posi_w1 = (const float*)d_in[12];
    const float* posi_b1 = (const float*)d_in[13];
    const float* posi_w2 = (const float*)d_in[14];
    const float* posi_b2 = (const float*)d_in[15];

    float* out_str   = (float*)d_out;
    float* out_coord = (float*)d_out + (size_t)N_NODES * RAW;

    void *p_edge_in, *p_bufA, *p_msg, *p_t2, *p_msum, *p_tsum, *p_cnt, *p_pin, *p_wt;
    cudaGetSymbolAddress(&p_edge_in, g_edge_in);
    cudaGetSymbolAddress(&p_bufA,    g_bufA);
    cudaGetSymbolAddress(&p_msg,     g_msg);
    cudaGetSymbolAddress(&p_t2,      g_t2);
    cudaGetSymbolAddress(&p_msum,    g_msum);
    cudaGetSymbolAddress(&p_tsum,    g_tsum);
    cudaGetSymbolAddress(&p_cnt,     g_cnt);
    cudaGetSymbolAddress(&p_pin,     g_pin);
    cudaGetSymbolAddress(&p_wt,      g_wt);
    float* wt = (float*)p_wt;

    const int DSM = 2 * STAGE_B;  // 64 KB
    cudaFuncSetAttribute(tgemm<true,false,true>,
                         cudaFuncAttributeMaxDynamicSharedMemorySize, DSM);
    cudaFuncSetAttribute(tgemm<false,true,false>,
                         cudaFuncAttributeMaxDynamicSharedMemorySize, DSM);

    cudaMemsetAsync(p_msum, 0, (size_t)N_NODES * HID * sizeof(float));
    cudaMemsetAsync(p_tsum, 0, (size_t)N_NODES * 3 * sizeof(float));
    cudaMemsetAsync(p_cnt,  0, (size_t)N_NODES * sizeof(float));

    transpose_w1<<<(256*KPAD + 255)/256, 256>>>(msg_w1, wt + WT1_OFF);
    transpose_round<<<(256*256 + 255)/256, 256>>>(msg_w2,  wt + WT2_OFF, 256, 256);
    transpose_round<<<(256*256 + 255)/256, 256>>>(tr_w1,   wt + WT3_OFF, 256, 256);
    transpose_round<<<(256*256 + 255)/256, 256>>>(tr_w2,   wt + WT4_OFF, 256, 256);
    transpose_round<<<(384*256 + 255)/256, 256>>>(posi_w1, wt + WT5_OFF, 384, 256);
    transpose_round<<<(256*128 + 255)/256, 256>>>(posi_w2, wt + WT6_OFF, 256, 128);

    gather_edges<<<N_EDGES / 8, 256>>>(ei, str, coord);

    const int MT_E = N_EDGES / 128;            // 5000
    const int MT_N = (N_NODES + 127) / 128;    // 391

    tgemm<true,false,true><<<dim3(2, MT_E), 256, DSM>>>(
        (const float*)p_edge_in, KPAD, wt + WT1_OFF, KPAD,
        (float*)p_bufA, HID, msg_b1, nullptr, 0, N_EDGES, KPAD);
    tgemm<true,false,true><<<dim3(2, MT_E), 256, DSM>>>(
        (const float*)p_bufA, HID, wt + WT2_OFF, HID,
        (float*)p_msg, HID, msg_b2, nullptr, 0, N_EDGES, HID);
    tgemm<true,false,true><<<dim3(2, MT_E), 256, DSM>>>(
        (const float*)p_msg, HID, wt + WT3_OFF, HID,
        (float*)p_bufA, HID, tr_b1, nullptr, 0, N_EDGES, HID);
    tgemm<true,false,true><<<dim3(2, MT_E), 256, DSM>>>(
        (const float*)p_bufA, HID, wt + WT4_OFF, HID,
        (float*)p_t2, HID, tr_b2, nullptr, 0, N_EDGES, HID);

    gate_scatter<<<N_EDGES / 8, 256>>>(ei, tr_w3);

    build_pin<<<(N_NODES * PIN_K + 255)/256, 256>>>(str);
    tgemm<true,false,true><<<dim3(2, MT_N), 256, DSM>>>(
        (const float*)p_pin, PIN_K, wt + WT5_OFF, PIN_K,
        (float*)p_bufA, HID, posi_b1, nullptr, 0, N_NODES, PIN_K);
    tgemm<false,true,false><<<dim3(1, MT_N), 256, DSM>>>(
        (const float*)p_bufA, HID, wt + WT6_OFF, HID,
        out_str, RAW, posi_b2, str, RAW, N_NODES, HID);

    coord_epilogue<<<(N_NODES * 3 + 255)/256, 256>>>(coord, out_coord);
}

// round 5
// speedup vs baseline: 4.3079x; 1.5451x over previous
#include <cuda_runtime.h>
#include <cuda_fp16.h>
#include <cstdint>
#include <math.h>

#define N_NODES 50000
#define N_EDGES 640000
#define RAW 128
#define HID 256
#define KPAD 320            // 2*RAW+1 = 257 padded to multiple of 64
#define PIN_K (RAW + HID)   // 384

// ---------------- scratch (device globals; no allocations allowed) ----------
__device__ __half g_edge_in[(size_t)N_EDGES * KPAD];
__device__ __half g_bufA[(size_t)N_EDGES * HID];
__device__ __half g_msg[(size_t)N_EDGES * HID];
__device__ __half g_t2[(size_t)N_EDGES * HID];
__device__ float  g_cdiff[(size_t)N_EDGES * 3];
__device__ float  g_msum[(size_t)N_NODES * HID];
__device__ float  g_tsum[(size_t)N_NODES * 3];
__device__ float  g_cnt[N_NODES];
__device__ __half g_pin[(size_t)N_NODES * PIN_K];
// transposed fp16 weights, [N,K] K-major, packed:
__device__ __half g_wt[409600];
#define WT1_OFF 0         // [256,320]
#define WT2_OFF 81920     // [256,256]
#define WT3_OFF 147456    // [256,256]
#define WT4_OFF 212992    // [256,256]
#define WT5_OFF 278528    // [256,384]
#define WT6_OFF 376832    // [128,256]

__device__ __forceinline__ float silu_f(float x) { return x / (1.0f + __expf(-x)); }

__device__ __forceinline__ uint32_t smem_u32(const void* p) {
    uint32_t a;
    asm("{ .reg .u64 t; cvta.to.shared.u64 t, %1; cvt.u32.u64 %0, t; }" : "=r"(a) : "l"(p));
    return a;
}
__device__ __forceinline__ void cp16(uint32_t dst, const void* src, uint32_t sz) {
    asm volatile("cp.async.cg.shared.global [%0], [%1], 16, %2;" :: "r"(dst), "l"(src), "r"(sz) : "memory");
}
__device__ __forceinline__ void ldsm4(uint32_t& r0, uint32_t& r1, uint32_t& r2, uint32_t& r3,
                                      uint32_t addr) {
    asm volatile("ldmatrix.sync.aligned.m8n8.x4.shared.b16 {%0,%1,%2,%3}, [%4];"
                 : "=r"(r0), "=r"(r1), "=r"(r2), "=r"(r3) : "r"(addr));
}

// ================= FP16 mma.sync GEMM, ldmatrix + cp.async pipeline =========
// C[M,Ntot] = act(A[M,K] @ Bt[Ntot,K]^T + bias) (+resid).
// A[M,K], Bt[Ntot,K] fp16 row-major. C fp16 (HOUT) or fp32.
// Tile 128x128, BK=64, 256 threads (8 warps, 2x4), 3-stage cp.async pipeline.
#define TILE_B 16384          // one 128x64 fp16 tile (128B rows)
#define STAGE_B (2 * TILE_B)  // A + B per stage
#define NSTG 3

template <bool ACT, bool RES, bool HOUT>
__global__ void __launch_bounds__(256, 2)
hgemm(const __half* __restrict__ A, int lda,
      const __half* __restrict__ Bt, int ldb,
      void* __restrict__ Cv, int ldc,
      const float* __restrict__ bias,
      const float* __restrict__ resid, int ldr,
      int M, int K)
{
    extern __shared__ char smem[];
    const uint32_t sb = smem_u32(smem);

    const int tid = threadIdx.x;
    const int wid = tid >> 5;
    const int lane = tid & 31;
    const int gid = lane >> 2;     // 0..7
    const int ctid = lane & 3;     // 0..3
    const int warpm = wid >> 2;    // 0..1 -> 64 rows
    const int warpn = wid & 3;     // 0..3 -> 32 cols

    const int bm = blockIdx.y * 128;
    const int bn = blockIdx.x * 128;
    const int KT = K >> 6;

    // ---- staging: thread t loads row t>>1, 4 chunks of 16B (8 halfs) ------
    const int sRow = tid >> 1;            // 0..127
    const int sHalf = tid & 1;            // 0..1
    const uint32_t sSw = (uint32_t)(sRow & 7);
    const bool aOK = (bm + sRow) < M;
    const __half* aSrcRow = A + (size_t)(aOK ? (bm + sRow) : 0) * lda + sHalf * 32;
    const __half* bSrcRow = Bt + (size_t)(bn + sRow) * ldb + sHalf * 32;
    const uint32_t aDstRow = sb + (uint32_t)sRow * 128;
    const uint32_t bDstRow = aDstRow + TILE_B;

    // ---- fragment (ldmatrix) addressing ------------------------------------
    const uint32_t fRow = (uint32_t)(lane & 15);
    const uint32_t fHi  = (uint32_t)(lane >> 4);
    const uint32_t fSx  = (uint32_t)(lane & 7);
    const uint32_t aFragBase = sb + ((uint32_t)warpm * 64 + fRow) * 128;
    const uint32_t bFragBase = sb + TILE_B + ((uint32_t)warpn * 32 + fRow) * 128;

    float acc[4][4][4];
    #pragma unroll
    for (int i = 0; i < 4; i++)
        #pragma unroll
        for (int j = 0; j < 4; j++)
            #pragma unroll
            for (int q = 0; q < 4; q++) acc[i][j][q] = 0.0f;

    auto stage_load = [&](int kt) {
        const uint32_t soff = (uint32_t)(kt % NSTG) * STAGE_B;
        const __half* aS = aSrcRow + kt * 64;
        const __half* bS = bSrcRow + kt * 64;
        #pragma unroll
        for (int i = 0; i < 4; i++) {
            const uint32_t c = (uint32_t)(sHalf * 4 + i);
            const uint32_t off = ((c ^ sSw) << 4);
            cp16(soff + aDstRow + off, aS + i * 8, aOK ? 16u : 0u);
            cp16(soff + bDstRow + off, bS + i * 8, 16u);
        }
        asm volatile("cp.async.commit_group;" ::: "memory");
    };

    stage_load(0);
    if (KT > 1) stage_load(1);

    for (int kt = 0; kt < KT; kt++) {
        if (kt + 2 < KT) {
            stage_load(kt + 2);
            asm volatile("cp.async.wait_group 2;" ::: "memory");
        } else {
            asm volatile("cp.async.wait_group 0;" ::: "memory");
        }
        __syncthreads();

        const uint32_t soff = (uint32_t)(kt % NSTG) * STAGE_B;
        #pragma unroll
        for (int kk = 0; kk < 4; kk++) {            // 4 x k16 steps
            const uint32_t kc = (uint32_t)(kk * 2); // 16B chunk base
            const uint32_t koff = (((kc + fHi) ^ fSx) << 4);
            uint32_t a[4][4], b[4][2];
            #pragma unroll
            for (int mf = 0; mf < 4; mf++)
                ldsm4(a[mf][0], a[mf][1], a[mf][2], a[mf][3],
                      soff + aFragBase + (uint32_t)mf * 2048 + koff);
            #pragma unroll
            for (int p = 0; p < 2; p++)
                ldsm4(b[2*p][0], b[2*p+1][0], b[2*p][1], b[2*p+1][1],
                      soff + bFragBase + (uint32_t)p * 2048 + koff);
            #pragma unroll
            for (int mf = 0; mf < 4; mf++)
                #pragma unroll
                for (int nf = 0; nf < 4; nf++) {
                    asm volatile(
                        "mma.sync.aligned.m16n8k16.row.col.f32.f16.f16.f32 "
                        "{%0,%1,%2,%3}, {%4,%5,%6,%7}, {%8,%9}, {%0,%1,%2,%3};"
                        : "+f"(acc[mf][nf][0]), "+f"(acc[mf][nf][1]),
                          "+f"(acc[mf][nf][2]), "+f"(acc[mf][nf][3])
                        : "r"(a[mf][0]), "r"(a[mf][1]), "r"(a[mf][2]), "r"(a[mf][3]),
                          "r"(b[nf][0]), "r"(b[nf][1]));
                }
        }
        __syncthreads();
    }

    // ---- epilogue -----------------------------------------------------------
    #pragma unroll
    for (int mf = 0; mf < 4; mf++) {
        #pragma unroll
        for (int nf = 0; nf < 4; nf++) {
            const int col0 = bn + warpn * 32 + nf * 8 + ctid * 2;
            const float b0 = bias[col0], b1 = bias[col0 + 1];
            #pragma unroll
            for (int h = 0; h < 2; h++) {
                const int row = bm + warpm * 64 + mf * 16 + gid + h * 8;
                if (row >= M) continue;
                float v0 = acc[mf][nf][h * 2 + 0] + b0;
                float v1 = acc[mf][nf][h * 2 + 1] + b1;
                if (ACT) { v0 = silu_f(v0); v1 = silu_f(v1); }
                if (RES) {
                    v0 += resid[(size_t)row * ldr + col0];
                    v1 += resid[(size_t)row * ldr + col0 + 1];
                }
                if (HOUT) {
                    __half2* out = (__half2*)((__half*)Cv + (size_t)row * ldc + col0);
                    *out = __floats2half2_rn(v0, v1);
                } else {
                    float2* out = (float2*)((float*)Cv + (size_t)row * ldc + col0);
                    *out = make_float2(v0, v1);
                }
            }
        }
    }
}

// ---------------- weight transpose -> fp16 -----------------------------------
__global__ void transpose_h(const float* __restrict__ in, __half* __restrict__ out,
                            int K, int N)
{   // in [K,N] -> out [N,K] fp16
    const int i = blockIdx.x * 256 + threadIdx.x;
    if (i >= K * N) return;
    const int n = i / K, k = i - n * K;
    out[i] = __float2half(in[(size_t)k * N + n]);
}
__global__ void transpose_w1(const float* __restrict__ w1, __half* __restrict__ out)
{   // w1 [257,256] -> out [256,320] fp16, zero-padded
    const int i = blockIdx.x * 256 + threadIdx.x;
    if (i >= 256 * KPAD) return;
    const int n = i / KPAD, k = i - n * KPAD;
    out[i] = (k < 2 * RAW + 1) ? __float2half(w1[(size_t)k * HID + n]) : __half(0.0f);
}

// ---------------- gather: build edge_in[E,320] fp16 + coord_diff -------------
__global__ void gather_edges(const int* __restrict__ ei,
                             const float* __restrict__ str,
                             const float* __restrict__ coord)
{
    const int e = blockIdx.x * 8 + (threadIdx.x >> 5);
    const int lane = threadIdx.x & 31;
    if (e >= N_EDGES) return;
    const int r = ei[e];
    const int c = ei[N_EDGES + e];

    const float4* sr = (const float4*)(str + (size_t)r * RAW);
    const float4* sc = (const float4*)(str + (size_t)c * RAW);
    float4 a = sr[lane], b = sc[lane];
    __half2 a01 = __floats2half2_rn(a.x, a.y), a23 = __floats2half2_rn(a.z, a.w);
    __half2 b01 = __floats2half2_rn(b.x, b.y), b23 = __floats2half2_rn(b.z, b.w);
    __half2* dst = (__half2*)(g_edge_in + (size_t)e * KPAD);
    dst[lane * 2 + 0]  = a01;  dst[lane * 2 + 1]  = a23;   // cols 0..127
    dst[64 + lane * 2] = b01;  dst[65 + lane * 2] = b23;   // cols 128..255

    if (lane == 0) {
        float dx = coord[r*3+0] - coord[c*3+0];
        float dy = coord[r*3+1] - coord[c*3+1];
        float dz = coord[r*3+2] - coord[c*3+2];
        g_cdiff[(size_t)e*3+0] = dx;
        g_cdiff[(size_t)e*3+1] = dy;
        g_cdiff[(size_t)e*3+2] = dz;
        dst[128] = __floats2half2_rn(dx*dx + dy*dy + dz*dz, 0.0f);  // cols 256,257
    } else {
        dst[128 + lane] = __floats2half2_rn(0.0f, 0.0f);            // cols 258..319
    }
}

// ---------------- per-edge gate = t2@w3; atomic segment scatter --------------
__global__ void gate_scatter(const int* __restrict__ ei,
                             const float* __restrict__ w3)
{
    const int e = blockIdx.x * 8 + (threadIdx.x >> 5);
    const int lane = threadIdx.x & 31;
    if (e >= N_EDGES) return;
    const int r = ei[e];

    const __half2* t2 = (const __half2*)(g_t2 + (size_t)e * HID);
    const float2*  w2 = (const float2*)w3;
    float acc = 0.0f;
    #pragma unroll
    for (int i = 0; i < 4; i++) {
        float2 tv = __half22float2(t2[lane + 32*i]);
        float2 wv = w2[lane + 32*i];
        acc += tv.x * wv.x + tv.y * wv.y;
    }
    #pragma unroll
    for (int o = 16; o > 0; o >>= 1) acc += __shfl_xor_sync(0xffffffffu, acc, o);

    if (lane < 3)
        atomicAdd(&g_tsum[(size_t)r*3 + lane], g_cdiff[(size_t)e*3 + lane] * acc);
    if (lane == 3)
        atomicAdd(&g_cnt[r], 1.0f);

    const __half2* msg = (const __half2*)(g_msg + (size_t)e * HID);
    #pragma unroll
    for (int i = 0; i < 4; i++) {
        float2 mv = __half22float2(msg[lane + 32*i]);
        atomicAdd(&g_msum[(size_t)r*HID + (lane + 32*i)*2 + 0], mv.x);
        atomicAdd(&g_msum[(size_t)r*HID + (lane + 32*i)*2 + 1], mv.y);
    }
}

// ---------------- build p_in = [str | msg_sum] fp16 --------------------------
__global__ void build_pin(const float* __restrict__ str)
{
    const int idx = blockIdx.x * 256 + threadIdx.x;
    if (idx >= N_NODES * PIN_K) return;
    const int n = idx / PIN_K;
    const int c = idx - n * PIN_K;
    g_pin[idx] = __float2half((c < RAW) ? str[(size_t)n*RAW + c]
                                        : g_msum[(size_t)n*HID + (c - RAW)]);
}

// ---------------- coord epilogue ---------------------------------------------
__global__ void coord_epilogue(const float* __restrict__ coord,
                               float* __restrict__ out_coord)
{
    const int idx = blockIdx.x * 256 + threadIdx.x;
    if (idx >= N_NODES * 3) return;
    const int n = idx / 3;
    out_coord[idx] = coord[idx] + g_tsum[idx] / fmaxf(g_cnt[n], 1.0f);
}

// ---------------- launch ------------------------------------------------------
extern "C" void kernel_launch(void* const* d_in, const int* in_sizes, int n_in,
                              void* d_out, int out_size)
{
    const int*   ei      = (const int*)  d_in[0];
    const float* str     = (const float*)d_in[1];
    const float* coord   = (const float*)d_in[2];
    const float* msg_w1  = (const float*)d_in[3];
    const float* msg_b1  = (const float*)d_in[4];
    const float* msg_w2  = (const float*)d_in[5];
    const float* msg_b2  = (const float*)d_in[6];
    const float* tr_w1   = (const float*)d_in[7];
    const float* tr_b1   = (const float*)d_in[8];
    const float* tr_w2   = (const float*)d_in[9];
    const float* tr_b2   = (const float*)d_in[10];
    const float* tr_w3   = (const float*)d_in[11];
    const float* posi_w1 = (const float*)d_in[12];
    const float* posi_b1 = (const float*)d_in[13];
    const float* posi_w2 = (const float*)d_in[14];
    const float* posi_b2 = (const float*)d_in[15];

    float* out_str   = (float*)d_out;
    float* out_coord = (float*)d_out + (size_t)N_NODES * RAW;

    void *p_edge_in, *p_bufA, *p_msg, *p_t2, *p_msum, *p_tsum, *p_cnt, *p_pin, *p_wt;
    cudaGetSymbolAddress(&p_edge_in, g_edge_in);
    cudaGetSymbolAddress(&p_bufA,    g_bufA);
    cudaGetSymbolAddress(&p_msg,     g_msg);
    cudaGetSymbolAddress(&p_t2,      g_t2);
    cudaGetSymbolAddress(&p_msum,    g_msum);
    cudaGetSymbolAddress(&p_tsum,    g_tsum);
    cudaGetSymbolAddress(&p_cnt,     g_cnt);
    cudaGetSymbolAddress(&p_pin,     g_pin);
    cudaGetSymbolAddress(&p_wt,      g_wt);
    __half* wt = (__half*)p_wt;

    const int DSM = NSTG * STAGE_B;  // 96 KB
    cudaFuncSetAttribute(hgemm<true,false,true>,
                         cudaFuncAttributeMaxDynamicSharedMemorySize, DSM);
    cudaFuncSetAttribute(hgemm<false,true,false>,
                         cudaFuncAttributeMaxDynamicSharedMemorySize, DSM);

    cudaMemsetAsync(p_msum, 0, (size_t)N_NODES * HID * sizeof(float));
    cudaMemsetAsync(p_tsum, 0, (size_t)N_NODES * 3 * sizeof(float));
    cudaMemsetAsync(p_cnt,  0, (size_t)N_NODES * sizeof(float));

    transpose_w1<<<(256*KPAD + 255)/256, 256>>>(msg_w1, wt + WT1_OFF);
    transpose_h<<<(256*256 + 255)/256, 256>>>(msg_w2,  wt + WT2_OFF, 256, 256);
    transpose_h<<<(256*256 + 255)/256, 256>>>(tr_w1,   wt + WT3_OFF, 256, 256);
    transpose_h<<<(256*256 + 255)/256, 256>>>(tr_w2,   wt + WT4_OFF, 256, 256);
    transpose_h<<<(384*256 + 255)/256, 256>>>(posi_w1, wt + WT5_OFF, 384, 256);
    transpose_h<<<(256*128 + 255)/256, 256>>>(posi_w2, wt + WT6_OFF, 256, 128);

    gather_edges<<<N_EDGES / 8, 256>>>(ei, str, coord);

    const int MT_E = N_EDGES / 128;            // 5000
    const int MT_N = (N_NODES + 127) / 128;    // 391

    hgemm<true,false,true><<<dim3(2, MT_E), 256, DSM>>>(
        (const __half*)p_edge_in, KPAD, wt + WT1_OFF, KPAD,
        p_bufA, HID, msg_b1, nullptr, 0, N_EDGES, KPAD);
    hgemm<true,false,true><<<dim3(2, MT_E), 256, DSM>>>(
        (const __half*)p_bufA, HID, wt + WT2_OFF, HID,
        p_msg, HID, msg_b2, nullptr, 0, N_EDGES, HID);
    hgemm<true,false,true><<<dim3(2, MT_E), 256, DSM>>>(
        (const __half*)p_msg, HID, wt + WT3_OFF, HID,
        p_bufA, HID, tr_b1, nullptr, 0, N_EDGES, HID);
    hgemm<true,false,true><<<dim3(2, MT_E), 256, DSM>>>(
        (const __half*)p_bufA, HID, wt + WT4_OFF, HID,
        p_t2, HID, tr_b2, nullptr, 0, N_EDGES, HID);

    gate_scatter<<<N_EDGES / 8, 256>>>(ei, tr_w3);

    build_pin<<<(N_NODES * PIN_K + 255)/256, 256>>>(str);
    hgemm<true,false,true><<<dim3(2, MT_N), 256, DSM>>>(
        (const __half*)p_pin, PIN_K, wt + WT5_OFF, PIN_K,
        p_bufA, HID, posi_b1, nullptr, 0, N_NODES, PIN_K);
    hgemm<false,true,false><<<dim3(1, MT_N), 256, DSM>>>(
        (const __half*)p_bufA, HID, wt + WT6_OFF, HID,
        out_str, RAW, posi_b2, str, RAW, N_NODES, HID);

    coord_epilogue<<<(N_NODES * 3 + 255)/256, 256>>>(coord, out_coord);
}